// round 16
// baseline (speedup 1.0000x reference)
#include <cuda_runtime.h>

// InvertAffine: (B, 3, 4) fp32 affine shift matrices.
// inverse top-3-rows = [R, -R t], R = (I3+A)^-1 via closed-form 3x3 adjugate.
//
// CONVERGED OPTIMUM (15 rounds; stable at 61.9-62.3 us wall, 57.7-58.9 us
// kernel, ~6.05 TB/s = 98-99% of the measured mixed 1:1 R/W HBM ceiling).
// - 512-matrix tile, 256 threads, 2 matrices/thread
// - split in/out smem buffers, 2 syncs
// - predicate-free, fully coalesced 6x LDG.128 / 6x STG.128 per thread
// - no cache hints (-8 us on sm_103a), no occupancy floor (reg cap
//   serializes the front-batched load run: -25% DRAM)
// Disproven limiters: L1tex (TMA variant), occupancy (46-93%), issue/ALU.

constexpr int TILE = 512;        // matrices per block
constexpr int TF4  = TILE * 3;   // 1536 float4 = 24 KB per buffer

__device__ __forceinline__ void invert3(const float4 a0, const float4 a1, const float4 a2,
                                        float4& q0, float4& q1, float4& q2)
{
    // M = I3 + A, t = last column
    const float m00 = a0.x + 1.0f, m01 = a0.y,        m02 = a0.z,        t0 = a0.w;
    const float m10 = a1.x,        m11 = a1.y + 1.0f, m12 = a1.z,        t1 = a1.w;
    const float m20 = a2.x,        m21 = a2.y,        m22 = a2.z + 1.0f, t2 = a2.w;

    const float c00 = m11 * m22 - m12 * m21;
    const float c10 = m12 * m20 - m10 * m22;
    const float c20 = m10 * m21 - m11 * m20;
    const float det = m00 * c00 + m01 * c10 + m02 * c20;
    const float rdet = 1.0f / det;

    const float i00 = c00 * rdet;
    const float i01 = (m02 * m21 - m01 * m22) * rdet;
    const float i02 = (m01 * m12 - m02 * m11) * rdet;
    const float i10 = c10 * rdet;
    const float i11 = (m00 * m22 - m02 * m20) * rdet;
    const float i12 = (m02 * m10 - m00 * m12) * rdet;
    const float i20 = c20 * rdet;
    const float i21 = (m01 * m20 - m00 * m21) * rdet;
    const float i22 = (m00 * m11 - m01 * m10) * rdet;

    const float o0 = -(i00 * t0 + i01 * t1 + i02 * t2);
    const float o1 = -(i10 * t0 + i11 * t1 + i12 * t2);
    const float o2 = -(i20 * t0 + i21 * t1 + i22 * t2);

    q0 = make_float4(i00, i01, i02, o0);
    q1 = make_float4(i10, i11, i12, o1);
    q2 = make_float4(i20, i21, i22, o2);
}

// Fast path: every tile full, zero predicates.
__global__ void __launch_bounds__(256) invert_affine_full_kernel(
    const float4* __restrict__ in, float4* __restrict__ out)
{
    __shared__ float4 s_in[TF4];
    __shared__ float4 s_out[TF4];

    const int t = threadIdx.x;
    const long long fbase = (long long)blockIdx.x * TF4;

    // 6 unguarded, front-batched, fully coalesced LDG.128 per thread
#pragma unroll
    for (int k = 0; k < 6; k++)
        s_in[t + k * 256] = in[fbase + t + k * 256];
    __syncthreads();

#pragma unroll
    for (int m = 0; m < 2; m++) {
        const int mi = t + m * 256;
        float4 q0, q1, q2;
        invert3(s_in[3 * mi + 0], s_in[3 * mi + 1], s_in[3 * mi + 2], q0, q1, q2);
        s_out[3 * mi + 0] = q0;
        s_out[3 * mi + 1] = q1;
        s_out[3 * mi + 2] = q2;
    }
    __syncthreads();

#pragma unroll
    for (int k = 0; k < 6; k++)
        out[fbase + t + k * 256] = s_out[t + k * 256];
}

// Tail: handles a final partial tile starting at matrix `mbase` (unused when
// B % 512 == 0, kept for generality).
__global__ void __launch_bounds__(256) invert_affine_tail_kernel(
    const float4* __restrict__ in, float4* __restrict__ out, int mbase, int b)
{
    __shared__ float4 s_in[TF4];
    __shared__ float4 s_out[TF4];

    const int t = threadIdx.x;
    const long long fbase = (long long)mbase * 3;
    const int nmat = b - mbase;
    const int nf4 = nmat * 3;

#pragma unroll
    for (int k = 0; k < 6; k++) {
        const int idx = t + k * 256;
        if (idx < nf4) s_in[idx] = in[fbase + idx];
    }
    __syncthreads();

#pragma unroll
    for (int m = 0; m < 2; m++) {
        const int mi = t + m * 256;
        if (mi < nmat) {
            float4 q0, q1, q2;
            invert3(s_in[3 * mi + 0], s_in[3 * mi + 1], s_in[3 * mi + 2], q0, q1, q2);
            s_out[3 * mi + 0] = q0;
            s_out[3 * mi + 1] = q1;
            s_out[3 * mi + 2] = q2;
        }
    }
    __syncthreads();

#pragma unroll
    for (int k = 0; k < 6; k++) {
        const int idx = t + k * 256;
        if (idx < nf4) out[fbase + idx] = s_out[idx];
    }
}

extern "C" void kernel_launch(void* const* d_in, const int* in_sizes, int n_in,
                              void* d_out, int out_size)
{
    const float4* in = (const float4*)d_in[0];
    float4* out = (float4*)d_out;
    const int b = in_sizes[0] / 12;  // (B, 3, 4) fp32 -> 12 elements per matrix

    const int full_tiles = b / TILE;        // 8192 for B = 4,194,304
    const int rem = b - full_tiles * TILE;  // 0 here

    if (full_tiles > 0)
        invert_affine_full_kernel<<<full_tiles, 256>>>(in, out);
    if (rem > 0)
        invert_affine_tail_kernel<<<1, 256>>>(in, out, full_tiles * TILE, b);
}

// round 17
// speedup vs baseline: 1.0005x; 1.0005x over previous
#include <cuda_runtime.h>

// InvertAffine: (B, 3, 4) fp32 affine shift matrices.
// inverse top-3-rows = [R, -R t], R = (I3+A)^-1 via closed-form 3x3 adjugate.
//
// FINAL CONVERGED OPTIMUM (16 rounds; reproducible 61.9-62.3 us wall,
// 57.7-58.9 us kernel, ~6.05 TB/s = 98-99% of the measured mixed 1:1 R/W
// HBM turnaround ceiling on this part).
// - 512-matrix tile, 256 threads, 2 matrices/thread
// - split in/out smem buffers, 2 syncs
// - predicate-free, fully coalesced 6x LDG.128 / 6x STG.128 per thread
// - no cache hints (measured -8 us), no occupancy floor (reg cap to 32
//   serializes the front-batched load run: measured -25% DRAM)
// Disproven limiters: L1tex (TMA variants), occupancy (46-93%), sync
// count, store epilogue. Traffic (96 B/matrix) and math (adjugate) minimal.

constexpr int TILE = 512;        // matrices per block
constexpr int TF4  = TILE * 3;   // 1536 float4 = 24 KB per buffer

__device__ __forceinline__ void invert3(const float4 a0, const float4 a1, const float4 a2,
                                        float4& q0, float4& q1, float4& q2)
{
    // M = I3 + A, t = last column
    const float m00 = a0.x + 1.0f, m01 = a0.y,        m02 = a0.z,        t0 = a0.w;
    const float m10 = a1.x,        m11 = a1.y + 1.0f, m12 = a1.z,        t1 = a1.w;
    const float m20 = a2.x,        m21 = a2.y,        m22 = a2.z + 1.0f, t2 = a2.w;

    const float c00 = m11 * m22 - m12 * m21;
    const float c10 = m12 * m20 - m10 * m22;
    const float c20 = m10 * m21 - m11 * m20;
    const float det = m00 * c00 + m01 * c10 + m02 * c20;
    const float rdet = 1.0f / det;

    const float i00 = c00 * rdet;
    const float i01 = (m02 * m21 - m01 * m22) * rdet;
    const float i02 = (m01 * m12 - m02 * m11) * rdet;
    const float i10 = c10 * rdet;
    const float i11 = (m00 * m22 - m02 * m20) * rdet;
    const float i12 = (m02 * m10 - m00 * m12) * rdet;
    const float i20 = c20 * rdet;
    const float i21 = (m01 * m20 - m00 * m21) * rdet;
    const float i22 = (m00 * m11 - m01 * m10) * rdet;

    const float o0 = -(i00 * t0 + i01 * t1 + i02 * t2);
    const float o1 = -(i10 * t0 + i11 * t1 + i12 * t2);
    const float o2 = -(i20 * t0 + i21 * t1 + i22 * t2);

    q0 = make_float4(i00, i01, i02, o0);
    q1 = make_float4(i10, i11, i12, o1);
    q2 = make_float4(i20, i21, i22, o2);
}

// Fast path: every tile full, zero predicates.
__global__ void __launch_bounds__(256) invert_affine_full_kernel(
    const float4* __restrict__ in, float4* __restrict__ out)
{
    __shared__ float4 s_in[TF4];
    __shared__ float4 s_out[TF4];

    const int t = threadIdx.x;
    const long long fbase = (long long)blockIdx.x * TF4;

    // 6 unguarded, front-batched, fully coalesced LDG.128 per thread
#pragma unroll
    for (int k = 0; k < 6; k++)
        s_in[t + k * 256] = in[fbase + t + k * 256];
    __syncthreads();

#pragma unroll
    for (int m = 0; m < 2; m++) {
        const int mi = t + m * 256;
        float4 q0, q1, q2;
        invert3(s_in[3 * mi + 0], s_in[3 * mi + 1], s_in[3 * mi + 2], q0, q1, q2);
        s_out[3 * mi + 0] = q0;
        s_out[3 * mi + 1] = q1;
        s_out[3 * mi + 2] = q2;
    }
    __syncthreads();

#pragma unroll
    for (int k = 0; k < 6; k++)
        out[fbase + t + k * 256] = s_out[t + k * 256];
}

// Tail: handles a final partial tile starting at matrix `mbase` (unused when
// B % 512 == 0, kept for generality).
__global__ void __launch_bounds__(256) invert_affine_tail_kernel(
    const float4* __restrict__ in, float4* __restrict__ out, int mbase, int b)
{
    __shared__ float4 s_in[TF4];
    __shared__ float4 s_out[TF4];

    const int t = threadIdx.x;
    const long long fbase = (long long)mbase * 3;
    const int nmat = b - mbase;
    const int nf4 = nmat * 3;

#pragma unroll
    for (int k = 0; k < 6; k++) {
        const int idx = t + k * 256;
        if (idx < nf4) s_in[idx] = in[fbase + idx];
    }
    __syncthreads();

#pragma unroll
    for (int m = 0; m < 2; m++) {
        const int mi = t + m * 256;
        if (mi < nmat) {
            float4 q0, q1, q2;
            invert3(s_in[3 * mi + 0], s_in[3 * mi + 1], s_in[3 * mi + 2], q0, q1, q2);
            s_out[3 * mi + 0] = q0;
            s_out[3 * mi + 1] = q1;
            s_out[3 * mi + 2] = q2;
        }
    }
    __syncthreads();

#pragma unroll
    for (int k = 0; k < 6; k++) {
        const int idx = t + k * 256;
        if (idx < nf4) out[fbase + idx] = s_out[idx];
    }
}

extern "C" void kernel_launch(void* const* d_in, const int* in_sizes, int n_in,
                              void* d_out, int out_size)
{
    const float4* in = (const float4*)d_in[0];
    float4* out = (float4*)d_out;
    const int b = in_sizes[0] / 12;  // (B, 3, 4) fp32 -> 12 elements per matrix

    const int full_tiles = b / TILE;        // 8192 for B = 4,194,304
    const int rem = b - full_tiles * TILE;  // 0 here

    if (full_tiles > 0)
        invert_affine_full_kernel<<<full_tiles, 256>>>(in, out);
    if (rem > 0)
        invert_affine_tail_kernel<<<1, 256>>>(in, out, full_tiles * TILE, b);
}